// round 14
// baseline (speedup 1.0000x reference)
#include <cuda_runtime.h>
#include <cstdint>

#define S_PER_BLK 4
#define T_STEPS   1024
#define H_DIM     64
#define G_DIM     256   // 4*H
#define D_DIM     4
#define NTHREADS  384   // 3 groups x 128
#define GRP       128
#define RING_D    4
#define RSTR      68    // padded ring row stride (floats) -> conflict-free scalar B-builds
#define H2S_STR   68    // padded h2 row stride

// named barrier ids (0 reserved for __syncthreads)
#define BAR_READY  1   // 1..4  (phase p)  G0 arrive / G1 sync, count 256
#define BAR_FREE   5   // 5..8  (phase p)  G1 arrive / G0 sync, count 256
#define BAR_H2RDY  9   // 9..10 (q)        G1 arrive / G2 sync, count 256
#define BAR_PART2  11  // 11..12 (q)       G2 arrive / G1 sync, count 256

typedef unsigned long long ull;

__device__ __forceinline__ void bar_sync(int id, int cnt) {
    asm volatile("bar.sync %0, %1;" :: "r"(id), "r"(cnt) : "memory");
}
__device__ __forceinline__ void bar_arrive(int id, int cnt) {
    asm volatile("bar.arrive %0, %1;" :: "r"(id), "r"(cnt) : "memory");
}

// ---- fast activations: single-MUFU tanh.approx ----
__device__ __forceinline__ float ftanh(float x) {
    float r;
    asm("tanh.approx.f32 %0, %1;" : "=f"(r) : "f"(x));
    return r;
}
__device__ __forceinline__ float fsig(float x) {
    float r;
    asm("tanh.approx.f32 %0, %1;" : "=f"(r) : "f"(0.5f * x));
    return __fmaf_rn(0.5f, r, 0.5f);
}

// ---- packed f32x2 fma (sm_100+) ----
__device__ __forceinline__ void fma2(ull& d, ull a, ull b, ull c) {
    asm("fma.rn.f32x2 %0, %1, %2, %3;" : "=l"(d) : "l"(a), "l"(b), "l"(c));
}
__device__ __forceinline__ float fold2(ull a) {
    float lo, hi;
    asm("mov.b64 {%0,%1}, %2;" : "=f"(lo), "=f"(hi) : "l"(a));
    return lo + hi;
}
__device__ __forceinline__ ull packf2(float lo, float hi) {
    ull r; asm("mov.b64 %0, {%1,%2};" : "=l"(r) : "f"(lo), "f"(hi)); return r;
}
__device__ __forceinline__ ull f4lo(const float4& v) {
    ull r; asm("mov.b64 %0, {%1,%2};" : "=l"(r) : "f"(v.x), "f"(v.y)); return r;
}
__device__ __forceinline__ ull f4hi(const float4& v) {
    ull r; asm("mov.b64 %0, {%1,%2};" : "=l"(r) : "f"(v.z), "f"(v.w)); return r;
}

// ---- tf32 warp MMA ----
__device__ __forceinline__ uint32_t cvt_tf32(float f) {
    uint32_t u;
    asm("cvt.rna.tf32.f32 %0, %1;" : "=r"(u) : "f"(f));
    return u;
}
__device__ __forceinline__ void mma_tf32(float& d0, float& d1, float& d2, float& d3,
                                         uint32_t a0, uint32_t a1, uint32_t a2, uint32_t a3,
                                         uint32_t b0, uint32_t b1) {
    asm volatile("mma.sync.aligned.m16n8k8.row.col.f32.tf32.tf32.f32 "
                 "{%0,%1,%2,%3}, {%4,%5,%6,%7}, {%8,%9}, {%0,%1,%2,%3};"
                 : "+f"(d0), "+f"(d1), "+f"(d2), "+f"(d3)
                 : "r"(a0), "r"(a1), "r"(a2), "r"(a3), "r"(b0), "r"(b1));
}

// Row permutation (G1/G2): fragment slab row 16*i + j  ->  W row 64*i + 16*warp + j.
// Tile i == gate type (0=i,1=f,2=g,3=o); lane group g owns units 16w+g, 16w+g+8.
// D-fragment of lane (g,tg): d[i][0]=(unit h0, sample 2tg), d[i][1]=(h0,2tg+1),
//                            d[i][2]=(h1, 2tg), d[i][3]=(h1, 2tg+1). Cols 4-7 dup.

// smem layout (floats):
//   xs   : S*T*D          = 16384
//   ring : RING_D*S*RSTR  = 1088   (h1 ring, G0 -> G1; classifier scratch after loop)
//   h2s  : 2*S*H2S_STR    = 544    (h2 double buffer)
//   pp   : 2*GRP*16       = 4096   (part2 D-fragments, thread-linear float4)
// total 22112 floats = 88448 bytes

__global__ __launch_bounds__(NTHREADS, 1)
void lstm_fused_kernel(const float* __restrict__ x,
                       const float* __restrict__ W_ih0,
                       const float* __restrict__ W_hh0,
                       const float* __restrict__ b0,
                       const float* __restrict__ W_ih1,
                       const float* __restrict__ W_hh1,
                       const float* __restrict__ b1,
                       const float* __restrict__ W_fc1,
                       const float* __restrict__ b_fc1,
                       const float* __restrict__ W_fc2,
                       const float* __restrict__ b_fc2,
                       float* __restrict__ out)
{
    extern __shared__ float sm[];
    float* xs   = sm;                                   // [S][T][D]
    float* ring = sm + S_PER_BLK * T_STEPS * D_DIM;     // [RING_D][S][RSTR]
    float* h2s  = ring + RING_D * S_PER_BLK * RSTR;     // [2][S][H2S_STR]
    float* pp   = h2s + 2 * S_PER_BLK * H2S_STR;        // [2][GRP][16]

    const int tid = threadIdx.x;
    const int bb  = blockIdx.x * S_PER_BLK;

    // ---- common staging ----
    {
        const float4* gx = (const float4*)(x + (size_t)bb * T_STEPS * D_DIM);
        float4*       sx = (float4*)xs;
        #pragma unroll 4
        for (int i = tid; i < S_PER_BLK * T_STEPS; i += NTHREADS) sx[i] = gx[i];
    }
    for (int i = tid; i < RING_D * S_PER_BLK * RSTR; i += NTHREADS) ring[i] = 0.f;
    for (int i = tid; i < 2 * S_PER_BLK * H2S_STR; i += NTHREADS) h2s[i] = 0.f;

    __syncthreads();

    if (tid < GRP) {
        // ===== G0: layer 0, scalar fma2 path (proven). (j, parity) rows =====
        const int j      = tid >> 1;
        const int parity = tid & 1;
        const int rA     = j + parity * 64;
        const int rB     = rA + 128;
        const float mulB = parity ? 0.5f : 1.0f;
        const float sclB = parity ? 0.5f : 1.0f;
        const float addB = parity ? 0.5f : 0.0f;

        float4 w0a[16], w0b[16];
        {
            const float4* pa = (const float4*)(W_hh0 + rA * H_DIM);
            const float4* pb = (const float4*)(W_hh0 + rB * H_DIM);
            #pragma unroll
            for (int i = 0; i < 16; i++) { w0a[i] = pa[i]; w0b[i] = pb[i]; }
        }
        float wiA[D_DIM], wiB[D_DIM];
        #pragma unroll
        for (int d = 0; d < D_DIM; d++) {
            wiA[d] = W_ih0[rA * D_DIM + d];
            wiB[d] = W_ih0[rB * D_DIM + d];
        }
        const float biasA = b0[rA];
        const float biasB = b0[rB];

        float c1a = 0.f, c1b = 0.f;

        for (int t = 0; t < T_STEPS; t++) {
            const int p = t & 3;
            bar_sync(BAR_FREE + p, 2 * GRP);

            const float* h1base = ring + ((t - 1) & 3) * S_PER_BLK * RSTR;

            float actA[S_PER_BLK], actB[S_PER_BLK];
            #pragma unroll
            for (int half = 0; half < 2; half++) {
                const int s0 = 2 * half, s1 = s0 + 1;
                const float4 xv0 = ((const float4*)xs)[s0 * T_STEPS + t];
                const float4 xv1 = ((const float4*)xs)[s1 * T_STEPS + t];

                float iA0 = biasA, iA1 = biasA, iB0 = biasB, iB1 = biasB;
                iA0 = __fmaf_rn(xv0.x, wiA[0], iA0); iA0 = __fmaf_rn(xv0.y, wiA[1], iA0);
                iA0 = __fmaf_rn(xv0.z, wiA[2], iA0); iA0 = __fmaf_rn(xv0.w, wiA[3], iA0);
                iA1 = __fmaf_rn(xv1.x, wiA[0], iA1); iA1 = __fmaf_rn(xv1.y, wiA[1], iA1);
                iA1 = __fmaf_rn(xv1.z, wiA[2], iA1); iA1 = __fmaf_rn(xv1.w, wiA[3], iA1);
                iB0 = __fmaf_rn(xv0.x, wiB[0], iB0); iB0 = __fmaf_rn(xv0.y, wiB[1], iB0);
                iB0 = __fmaf_rn(xv0.z, wiB[2], iB0); iB0 = __fmaf_rn(xv0.w, wiB[3], iB0);
                iB1 = __fmaf_rn(xv1.x, wiB[0], iB1); iB1 = __fmaf_rn(xv1.y, wiB[1], iB1);
                iB1 = __fmaf_rn(xv1.z, wiB[2], iB1); iB1 = __fmaf_rn(xv1.w, wiB[3], iB1);

                ull aA0 = packf2(iA0, 0.f), aA1 = packf2(iA1, 0.f);
                ull aB0 = packf2(iB0, 0.f), aB1 = packf2(iB1, 0.f);
                const float4* h1p0 = (const float4*)(h1base + s0 * RSTR);
                const float4* h1p1 = (const float4*)(h1base + s1 * RSTR);
                #pragma unroll
                for (int k = 0; k < 16; k++) {
                    const float4 hv0 = h1p0[k];
                    const float4 hv1 = h1p1[k];
                    fma2(aA0, f4lo(w0a[k]), f4lo(hv0), aA0);
                    fma2(aA0, f4hi(w0a[k]), f4hi(hv0), aA0);
                    fma2(aA1, f4lo(w0a[k]), f4lo(hv1), aA1);
                    fma2(aA1, f4hi(w0a[k]), f4hi(hv1), aA1);
                    fma2(aB0, f4lo(w0b[k]), f4lo(hv0), aB0);
                    fma2(aB0, f4hi(w0b[k]), f4hi(hv0), aB0);
                    fma2(aB1, f4lo(w0b[k]), f4lo(hv1), aB1);
                    fma2(aB1, f4hi(w0b[k]), f4hi(hv1), aB1);
                }
                actA[s0] = fsig(fold2(aA0));
                actA[s1] = fsig(fold2(aA1));
                actB[s0] = __fmaf_rn(sclB, ftanh(fold2(aB0) * mulB), addB);
                actB[s1] = __fmaf_rn(sclB, ftanh(fold2(aB1) * mulB), addB);
            }

            float rxA[S_PER_BLK], rxB[S_PER_BLK];
            #pragma unroll
            for (int s = 0; s < S_PER_BLK; s++) {
                rxA[s] = __shfl_xor_sync(0xffffffffu, actA[s], 1);
                rxB[s] = __shfl_xor_sync(0xffffffffu, actB[s], 1);
            }

            float* rp = ring + p * S_PER_BLK * RSTR;
            if (parity == 0) {
                c1a = __fmaf_rn(rxA[0], c1a, actA[0] * actB[0]);
                rp[0 * RSTR + j] = rxB[0] * ftanh(c1a);
                c1b = __fmaf_rn(rxA[1], c1b, actA[1] * actB[1]);
                rp[1 * RSTR + j] = rxB[1] * ftanh(c1b);
            } else {
                c1a = __fmaf_rn(actA[2], c1a, rxA[2] * rxB[2]);
                rp[2 * RSTR + j] = actB[2] * ftanh(c1a);
                c1b = __fmaf_rn(actA[3], c1b, rxA[3] * rxB[3]);
                rp[3 * RSTR + j] = actB[3] * ftanh(c1b);
            }
            bar_arrive(BAR_READY + p, 2 * GRP);
        }
    } else if (tid < 2 * GRP) {
        // ===== G1: layer-1 critical path via tf32 MMA (permuted rows) =====
        const int t1   = tid - GRP;
        const int warp = t1 >> 5;
        const int lane = t1 & 31;
        const int g    = lane >> 2;
        const int tg   = lane & 3;
        const int s    = g & 3;                 // B column (samples, cols 4-7 dup)
        const int h0   = 16 * warp + g;
        const int h1u  = h0 + 8;

        // A fragments: W_ih1 permuted rows (tile i = gate i), tf32, 128 regs
        uint32_t A[4][8][4];
        #pragma unroll
        for (int i = 0; i < 4; i++) {
            const float* wr1 = W_ih1 + (64 * i + h0) * H_DIM;
            const float* wr2 = W_ih1 + (64 * i + h1u) * H_DIM;
            #pragma unroll
            for (int jj = 0; jj < 8; jj++) {
                const int k = 8 * jj + tg;
                A[i][jj][0] = cvt_tf32(wr1[k]);
                A[i][jj][1] = cvt_tf32(wr2[k]);
                A[i][jj][2] = cvt_tf32(wr1[k + 4]);
                A[i][jj][3] = cvt_tf32(wr2[k + 4]);
            }
        }

        const int sA = 2 * tg, sB = 2 * tg + 1;  // valid for tg<2
        float c2[4] = {0.f, 0.f, 0.f, 0.f};      // (h0,sA),(h0,sB),(h1,sA),(h1,sB)

        #pragma unroll
        for (int p = 0; p < RING_D; p++) bar_arrive(BAR_FREE + p, 2 * GRP);
        bar_arrive(BAR_H2RDY + 1, 2 * GRP);

        for (int t = 0; t < T_STEPS; t++) {
            const int p = t & 3;
            const int q = t & 1;

            bar_sync(BAR_READY + p, 2 * GRP);    // h1(t) ready

            const float* h1r = ring + p * S_PER_BLK * RSTR + s * RSTR;
            float d[4][4] = {};
            #pragma unroll
            for (int jj = 0; jj < 8; jj++) {
                const uint32_t b0v = cvt_tf32(h1r[8 * jj + tg]);
                const uint32_t b1v = cvt_tf32(h1r[8 * jj + tg + 4]);
                #pragma unroll
                for (int i = 0; i < 4; i++) {
                    mma_tf32(d[i][0], d[i][1], d[i][2], d[i][3],
                             A[i][jj][0], A[i][jj][1], A[i][jj][2], A[i][jj][3],
                             b0v, b1v);
                }
            }
            bar_arrive(BAR_FREE + p, 2 * GRP);   // done reading ring[p]

            bar_sync(BAR_PART2 + q, 2 * GRP);    // part2(t) fragments ready

            if (tg < 2) {
                const float4* pq = (const float4*)pp + q * GRP * 4 + t1 * 4;
                const float4 pi = pq[0], pf = pq[1], pg = pq[2], po = pq[3];

                float* hq = h2s + q * S_PER_BLK * H2S_STR;

                // (h0, sA)
                {
                    const float iv = fsig(d[0][0] + pi.x);
                    const float fv = fsig(d[1][0] + pf.x);
                    const float gv = ftanh(d[2][0] + pg.x);
                    const float ov = fsig(d[3][0] + po.x);
                    c2[0] = __fmaf_rn(fv, c2[0], iv * gv);
                    hq[sA * H2S_STR + h0] = ov * ftanh(c2[0]);
                }
                // (h0, sB)
                {
                    const float iv = fsig(d[0][1] + pi.y);
                    const float fv = fsig(d[1][1] + pf.y);
                    const float gv = ftanh(d[2][1] + pg.y);
                    const float ov = fsig(d[3][1] + po.y);
                    c2[1] = __fmaf_rn(fv, c2[1], iv * gv);
                    hq[sB * H2S_STR + h0] = ov * ftanh(c2[1]);
                }
                // (h1u, sA)
                {
                    const float iv = fsig(d[0][2] + pi.z);
                    const float fv = fsig(d[1][2] + pf.z);
                    const float gv = ftanh(d[2][2] + pg.z);
                    const float ov = fsig(d[3][2] + po.z);
                    c2[2] = __fmaf_rn(fv, c2[2], iv * gv);
                    hq[sA * H2S_STR + h1u] = ov * ftanh(c2[2]);
                }
                // (h1u, sB)
                {
                    const float iv = fsig(d[0][3] + pi.w);
                    const float fv = fsig(d[1][3] + pf.w);
                    const float gv = ftanh(d[2][3] + pg.w);
                    const float ov = fsig(d[3][3] + po.w);
                    c2[3] = __fmaf_rn(fv, c2[3], iv * gv);
                    hq[sB * H2S_STR + h1u] = ov * ftanh(c2[3]);
                }
            }
            bar_arrive(BAR_H2RDY + q, 2 * GRP);  // publish h2(t)
        }
    } else {
        // ===== G2: shadow via tf32 MMA (same permuted rows), fragments -> pp =====
        const int t2   = tid - 2 * GRP;
        const int warp = t2 >> 5;
        const int lane = t2 & 31;
        const int g    = lane >> 2;
        const int tg   = lane & 3;
        const int s    = g & 3;
        const int h0   = 16 * warp + g;
        const int h1u  = h0 + 8;

        uint32_t A[4][8][4];
        #pragma unroll
        for (int i = 0; i < 4; i++) {
            const float* wr1 = W_hh1 + (64 * i + h0) * H_DIM;
            const float* wr2 = W_hh1 + (64 * i + h1u) * H_DIM;
            #pragma unroll
            for (int jj = 0; jj < 8; jj++) {
                const int k = 8 * jj + tg;
                A[i][jj][0] = cvt_tf32(wr1[k]);
                A[i][jj][1] = cvt_tf32(wr2[k]);
                A[i][jj][2] = cvt_tf32(wr1[k + 4]);
                A[i][jj][3] = cvt_tf32(wr2[k + 4]);
            }
        }
        float biasLo[4], biasHi[4];
        #pragma unroll
        for (int i = 0; i < 4; i++) {
            biasLo[i] = b1[64 * i + h0];
            biasHi[i] = b1[64 * i + h1u];
        }

        for (int t = 0; t < T_STEPS; t++) {
            const int q  = t & 1;
            const int qr = (t - 1) & 1;          // h2(t-1): t=0 -> h2s[1] (zeros)

            bar_sync(BAR_H2RDY + qr, 2 * GRP);   // h2(t-1) ready

            const float* h2p = h2s + qr * S_PER_BLK * H2S_STR + s * H2S_STR;
            float d[4][4];
            #pragma unroll
            for (int i = 0; i < 4; i++) {
                d[i][0] = biasLo[i]; d[i][1] = biasLo[i];
                d[i][2] = biasHi[i]; d[i][3] = biasHi[i];
            }
            #pragma unroll
            for (int jj = 0; jj < 8; jj++) {
                const uint32_t b0v = cvt_tf32(h2p[8 * jj + tg]);
                const uint32_t b1v = cvt_tf32(h2p[8 * jj + tg + 4]);
                #pragma unroll
                for (int i = 0; i < 4; i++) {
                    mma_tf32(d[i][0], d[i][1], d[i][2], d[i][3],
                             A[i][jj][0], A[i][jj][1], A[i][jj][2], A[i][jj][3],
                             b0v, b1v);
                }
            }
            // dump D fragments thread-linear (G1 lane t1==t2 reads the same slot)
            float4* pq = (float4*)pp + q * GRP * 4 + t2 * 4;
            #pragma unroll
            for (int i = 0; i < 4; i++)
                pq[i] = make_float4(d[i][0], d[i][1], d[i][2], d[i][3]);
            bar_arrive(BAR_PART2 + q, 2 * GRP);  // part2(t) published
        }
    }

    __syncthreads();

    // ---------- classifier (ring reused as scratch); h2 final in h2s[1] ----------
    const float* h2f = h2s + ((T_STEPS - 1) & 1) * S_PER_BLK * H2S_STR;
    if (tid < S_PER_BLK * 32) {
        int s = tid >> 5, jj = tid & 31;
        float a = b_fc1[jj];
        #pragma unroll
        for (int k = 0; k < H_DIM; k++)
            a = __fmaf_rn(h2f[s * H2S_STR + k], W_fc1[jj * H_DIM + k], a);
        ring[s * 32 + jj] = fmaxf(a, 0.f);
    }
    __syncthreads();
    if (tid < S_PER_BLK) {
        float a = b_fc2[0];
        #pragma unroll
        for (int jj = 0; jj < 32; jj++)
            a = __fmaf_rn(ring[tid * 32 + jj], W_fc2[jj], a);
        out[bb + tid] = fsig(a);
    }
}

extern "C" void kernel_launch(void* const* d_in, const int* in_sizes, int n_in,
                              void* d_out, int out_size)
{
    const float* x     = (const float*)d_in[0];
    const float* W_ih0 = (const float*)d_in[1];
    const float* W_hh0 = (const float*)d_in[2];
    const float* b0    = (const float*)d_in[3];
    const float* W_ih1 = (const float*)d_in[4];
    const float* W_hh1 = (const float*)d_in[5];
    const float* b1    = (const float*)d_in[6];
    const float* W_fc1 = (const float*)d_in[7];
    const float* b_fc1 = (const float*)d_in[8];
    const float* W_fc2 = (const float*)d_in[9];
    const float* b_fc2 = (const float*)d_in[10];
    float* out = (float*)d_out;

    const size_t smem_bytes =
        (size_t)(S_PER_BLK * T_STEPS * D_DIM          // xs
                 + RING_D * S_PER_BLK * RSTR          // ring
                 + 2 * S_PER_BLK * H2S_STR            // h2s
                 + 2 * GRP * 16)                      // pp
        * sizeof(float);

    cudaFuncSetAttribute(lstm_fused_kernel,
                         cudaFuncAttributeMaxDynamicSharedMemorySize,
                         (int)smem_bytes);

    const int nblocks = 512 / S_PER_BLK;   // 128
    lstm_fused_kernel<<<nblocks, NTHREADS, smem_bytes>>>(
        x, W_ih0, W_hh0, b0, W_ih1, W_hh1, b1,
        W_fc1, b_fc1, W_fc2, b_fc2, out);
}